// round 9
// baseline (speedup 1.0000x reference)
#include <cuda_runtime.h>
#include <math.h>

#define SS 512
#define BB 64
#define II 1024
#define HH 1024
#define G4 4096   // 4*H
#define BHH (BB * HH)

#define NKB 8          // K-split factor for the step GEMM
#define NNB 16         // n-blocks (gate-coherent, 64 h-cols each)
#define BKC 128        // k-span per step-GEMM block (1024/8)
#define BKS 16         // k per smem stage

// Scratch: xW for all timesteps, k-split partials, ping-pong cell state.
__device__ float g_xw[(size_t)SS * BB * G4];       // 512 MB
__device__ float g_part[NKB][BB * G4];             // 8 MB
__device__ float g_c[2][BHH];
__device__ unsigned g_nbcnt[NNB];                  // monotonic per-step-step
__device__ unsigned g_stepcnt;                     // monotonic

__device__ __forceinline__ float sigf(float x) {
    return 1.0f / (1.0f + __expf(-x));
}
__device__ __forceinline__ float tanhfast(float x) {
    return fmaf(2.0f, sigf(2.0f * x), -1.0f);
}

typedef unsigned long long ull;

__device__ __forceinline__ void fma2(ull& d, ull a, ull b) {
    asm("fma.rn.f32x2 %0, %1, %2, %0;" : "+l"(d) : "l"(a), "l"(b));
}
__device__ __forceinline__ float2 u2f(ull v) {
    float2 r;
    asm("mov.b64 {%0, %1}, %2;" : "=f"(r.x), "=f"(r.y) : "l"(v));
    return r;
}

// ---------------------------------------------------------------------------
// Kernel A: g_xw[m, g] = sum_i X[m, i] * W[g, i] + bias[g]   (unchanged)
// ---------------------------------------------------------------------------
__global__ __launch_bounds__(256) void gemm_xw(const float* __restrict__ X,
                                               const float* __restrict__ W,
                                               const float* __restrict__ bias) {
    __shared__ __align__(16) float As[32][68];
    __shared__ __align__(16) float Bs[32][68];

    const int m0 = blockIdx.y * 64;
    const int n0 = blockIdx.x * 64;
    const int tid = threadIdx.x;
    const int tx = tid & 15;
    const int ty = tid >> 4;
    const int r  = tid >> 3;
    const int kv = (tid & 7) << 2;

    float acc[4][4] = {};

    for (int k0 = 0; k0 < II; k0 += 32) {
        float4 a0 = *(const float4*)(X + (size_t)(m0 + r)      * II + k0 + kv);
        float4 a1 = *(const float4*)(X + (size_t)(m0 + r + 32) * II + k0 + kv);
        float4 b0 = *(const float4*)(W + (size_t)(n0 + r)      * II + k0 + kv);
        float4 b1 = *(const float4*)(W + (size_t)(n0 + r + 32) * II + k0 + kv);

        As[kv+0][r] = a0.x; As[kv+1][r] = a0.y; As[kv+2][r] = a0.z; As[kv+3][r] = a0.w;
        As[kv+0][r+32] = a1.x; As[kv+1][r+32] = a1.y; As[kv+2][r+32] = a1.z; As[kv+3][r+32] = a1.w;
        Bs[kv+0][r] = b0.x; Bs[kv+1][r] = b0.y; Bs[kv+2][r] = b0.z; Bs[kv+3][r] = b0.w;
        Bs[kv+0][r+32] = b1.x; Bs[kv+1][r+32] = b1.y; Bs[kv+2][r+32] = b1.z; Bs[kv+3][r+32] = b1.w;
        __syncthreads();

        #pragma unroll
        for (int k = 0; k < 32; k++) {
            float4 av = *(const float4*)&As[k][ty << 2];
            float4 bv = *(const float4*)&Bs[k][tx << 2];
            float am[4] = {av.x, av.y, av.z, av.w};
            float bn[4] = {bv.x, bv.y, bv.z, bv.w};
            #pragma unroll
            for (int i = 0; i < 4; i++)
                #pragma unroll
                for (int j = 0; j < 4; j++)
                    acc[i][j] += am[i] * bn[j];
        }
        __syncthreads();
    }

    const int nn = n0 + (tx << 2);
    float4 bsv = *(const float4*)(bias + nn);
    float bb4[4] = {bsv.x, bsv.y, bsv.z, bsv.w};
    #pragma unroll
    for (int i = 0; i < 4; i++) {
        const int m = m0 + (ty << 2) + i;
        float4 ov;
        ov.x = acc[i][0] + bb4[0];
        ov.y = acc[i][1] + bb4[1];
        ov.z = acc[i][2] + bb4[2];
        ov.w = acc[i][3] + bb4[3];
        *(float4*)(g_xw + (size_t)m * G4 + nn) = ov;
    }
}

// ---------------------------------------------------------------------------
// Kernel B: PERSISTENT LSTM — one launch runs all 512 steps.
//   128 blocks (single wave, guaranteed co-resident), 256 threads.
//   Block bid: nb = bid>>3 (gate-coherent 64 h-cols), kb = bid&7 (k-split).
//   Per step:
//     Phase 1: partial GEMM 64m x 256n x 128k, FFMA2, 8x8 thread tiles.
//              U is L1-resident after step 0 (L1 persists within launch).
//     nb-group sync via monotonic counter, then ALL 8 kb-blocks combine
//              (8 h-cols each): sum partials (__ldcg) + xW, gates, c, h.
//     Grid step barrier via monotonic counter before next step reads h.
// ---------------------------------------------------------------------------
__global__ __launch_bounds__(256) void lstm_persist(const float* __restrict__ h0,
                                                    const float* __restrict__ U,
                                                    float* __restrict__ out) {
    __shared__ __align__(16) float Ad[BKS][140];    // h duplicated: [k][2m(+pad)]
    __shared__ __align__(16) float Bs[BKS][264];    // U: [k][c(+pad)]

    const int bid = blockIdx.x;
    const int nb = bid >> 3;              // 0..15
    const int kb = bid & 7;               // 0..7
    const int kbase = kb * BKC;
    const int tid = threadIdx.x;
    const int tx = tid & 31;              // n-group
    const int ty = tid >> 5;              // m-group (8 rows)

    // A loader indices
    const int ar = tid >> 2;                  // 0..63
    const int ak = (tid & 3) << 2;            // 0,4,8,12

    // B loader: 4 gate groups of 64 rows x 16 k
    const int ur = tid >> 2;
    const int uk = (tid & 3) << 2;
    const float* uP = U + (size_t)((nb << 6) + ur) * HH + kbase + uk;
    const size_t ugstr = (size_t)1024 * HH;   // next gate

    // Partial store indices
    const int gidxA = ((tx >> 4) << 10) + (nb << 6) + ((tx & 15) << 2);

    // Combine indices: h-cols [nb*64 + kb*8, +8)
    const int cb  = tid >> 2;                 // batch 0..63
    const int hcol = (nb << 6) + (kb << 3) + ((tid & 3) << 1);

    for (int t = 0; t < SS; t++) {
        const float* hprev = t ? (out + (size_t)(t - 1) * BHH) : h0;
        const int par = t & 1;

        // ---------------- Phase 1: partial GEMM ----------------
        const float* aP = hprev + (size_t)ar * HH + kbase + ak;

        float4 ha  = *(const float4*)(aP);
        float4 ub0 = *(const float4*)(uP);
        float4 ub1 = *(const float4*)(uP + ugstr);
        float4 ub2 = *(const float4*)(uP + 2 * ugstr);
        float4 ub3 = *(const float4*)(uP + 3 * ugstr);

        ull acc[8][4];
        #pragma unroll
        for (int i = 0; i < 8; i++)
            #pragma unroll
            for (int j = 0; j < 4; j++) acc[i][j] = 0ull;

        for (int s = 0; s < BKC; s += BKS) {
            #pragma unroll
            for (int i = 0; i < 4; i++) {
                const float av = (&ha.x)[i];
                Ad[ak + i][2 * ar]     = av;
                Ad[ak + i][2 * ar + 1] = av;
                Bs[uk + i][ur]       = (&ub0.x)[i];
                Bs[uk + i][ur + 64]  = (&ub1.x)[i];
                Bs[uk + i][ur + 128] = (&ub2.x)[i];
                Bs[uk + i][ur + 192] = (&ub3.x)[i];
            }
            __syncthreads();

            if (s + BKS < BKC) {
                ha  = *(const float4*)(aP + s + BKS);
                ub0 = *(const float4*)(uP + s + BKS);
                ub1 = *(const float4*)(uP + ugstr + s + BKS);
                ub2 = *(const float4*)(uP + 2 * ugstr + s + BKS);
                ub3 = *(const float4*)(uP + 3 * ugstr + s + BKS);
            }

            #pragma unroll
            for (int k = 0; k < BKS; k++) {
                ull a2[8];
                #pragma unroll
                for (int i2 = 0; i2 < 4; i2++) {
                    const ulonglong2 aa =
                        *(const ulonglong2*)&Ad[k][(ty << 4) + (i2 << 2)];
                    a2[2 * i2]     = aa.x;
                    a2[2 * i2 + 1] = aa.y;
                }
                const ulonglong2 bb0 = *(const ulonglong2*)&Bs[k][tx << 2];
                const ulonglong2 bb1 = *(const ulonglong2*)&Bs[k][128 + (tx << 2)];
                ull b2[4] = {bb0.x, bb0.y, bb1.x, bb1.y};

                #pragma unroll
                for (int i = 0; i < 8; i++) {
                    fma2(acc[i][0], a2[i], b2[0]);
                    fma2(acc[i][1], a2[i], b2[1]);
                    fma2(acc[i][2], a2[i], b2[2]);
                    fma2(acc[i][3], a2[i], b2[3]);
                }
            }
            __syncthreads();
        }

        // Store partials at global gate indices.
        {
            float* pout = g_part[kb];
            #pragma unroll
            for (int i = 0; i < 8; i++) {
                const int m = (ty << 3) + i;
                const float2 p0 = u2f(acc[i][0]);
                const float2 p1 = u2f(acc[i][1]);
                const float2 p2 = u2f(acc[i][2]);
                const float2 p3 = u2f(acc[i][3]);
                float4 oA = {p0.x, p0.y, p1.x, p1.y};
                float4 oB = {p2.x, p2.y, p3.x, p3.y};
                *(float4*)(pout + (size_t)m * G4 + gidxA)        = oA;
                *(float4*)(pout + (size_t)m * G4 + gidxA + 2048) = oB;
            }
        }

        // ---------------- nb-group sync ----------------
        __threadfence();
        __syncthreads();
        if (tid == 0) {
            atomicAdd(&g_nbcnt[nb], 1u);
            while (atomicAdd(&g_nbcnt[nb], 0u) < 8u * (unsigned)(t + 1)) {
                __nanosleep(32);
            }
        }
        __syncthreads();

        // ---------------- Phase 2: combine (all blocks, 8 cols each) -------
        {
            float2 gate[4];
            #pragma unroll
            for (int g = 0; g < 4; g++) {
                const size_t off = (size_t)cb * G4 + (g << 10) + hcol;
                float2 s = *(const float2*)(g_xw + (size_t)t * BB * G4 + off);
                #pragma unroll
                for (int p = 0; p < NKB; p++) {
                    const float2 pv = __ldcg((const float2*)(g_part[p] + off));
                    s.x += pv.x; s.y += pv.y;
                }
                gate[g] = s;
            }

            const int idx = cb * HH + hcol;
            const float2 cp = *(const float2*)(g_c[par] + idx);
            float2 cn, hv;
            {
                const float iv = sigf(gate[0].x), fv = sigf(gate[1].x);
                const float gv = tanhfast(gate[2].x), ov = sigf(gate[3].x);
                cn.x = fv * cp.x + iv * gv;  hv.x = ov * tanhfast(cn.x);
            }
            {
                const float iv = sigf(gate[0].y), fv = sigf(gate[1].y);
                const float gv = tanhfast(gate[2].y), ov = sigf(gate[3].y);
                cn.y = fv * cp.y + iv * gv;  hv.y = ov * tanhfast(cn.y);
            }
            *(float2*)(g_c[par ^ 1] + idx) = cn;
            *(float2*)(out + (size_t)t * BHH + idx) = hv;
        }

        // ---------------- grid step barrier ----------------
        __threadfence();
        __syncthreads();
        if (tid == 0) {
            atomicAdd(&g_stepcnt, 1u);
            if (t + 1 < SS) {
                while (atomicAdd(&g_stepcnt, 0u) < 128u * (unsigned)(t + 1)) {
                    __nanosleep(32);
                }
            }
        }
        __syncthreads();
    }
}

// ---------------------------------------------------------------------------
// Helpers: seed c buffer + reset counters; emit h_t / c_t tails.
// ---------------------------------------------------------------------------
__global__ void copy_c0(const float* __restrict__ c0) {
    const int i = blockIdx.x * 256 + threadIdx.x;
    g_c[0][i] = c0[i];
    if (blockIdx.x == 0) {
        if (threadIdx.x < NNB) g_nbcnt[threadIdx.x] = 0u;
        if (threadIdx.x == NNB) g_stepcnt = 0u;
    }
}

__global__ void finalize(float* __restrict__ out) {
    const int i = blockIdx.x * 256 + threadIdx.x;
    const size_t base = (size_t)SS * BHH;
    out[base + i] = out[(size_t)(SS - 1) * BHH + i];   // h_t
    out[base + BHH + i] = g_c[0][i];                   // c_t (S even)
}

// ---------------------------------------------------------------------------
extern "C" void kernel_launch(void* const* d_in, const int* in_sizes, int n_in,
                              void* d_out, int out_size) {
    (void)in_sizes; (void)n_in; (void)out_size;
    const float* x  = (const float*)d_in[0];
    const float* h0 = (const float*)d_in[1];
    const float* c0 = (const float*)d_in[2];
    const float* Ww = (const float*)d_in[3];
    const float* Wb = (const float*)d_in[4];
    const float* Uw = (const float*)d_in[5];
    float* out = (float*)d_out;

    copy_c0<<<(BB * HH) / 256, 256>>>(c0);

    gemm_xw<<<dim3(G4 / 64, (SS * BB) / 64), 256>>>(x, Ww, Wb);

    lstm_persist<<<NNB * NKB, 256>>>(h0, Uw, out);

    finalize<<<(BB * HH) / 256, 256>>>(out);
}

// round 11
// speedup vs baseline: 1.4654x; 1.4654x over previous
#include <cuda_runtime.h>
#include <cuda_bf16.h>
#include <math.h>
#include <stdint.h>

#define SS 512
#define BB 64
#define II 1024
#define HH 1024
#define G4 4096   // 4*H
#define BHH (BB * HH)

#define NKB 8          // K-split factor for the step GEMM
#define NNB 16         // n-blocks (gate-coherent, 64 h-cols each)
#define BKC 128        // k-span per step-GEMM block (1024/8)
#define BKS 16         // k per smem stage

// Scratch
__device__ float g_xw[(size_t)SS * BB * G4];       // 512 MB
__device__ float g_part[NKB][BB * G4];             // 8 MB
__device__ float g_c[2][BHH];
__device__ unsigned g_nbcnt[NNB];
__device__ unsigned g_stepcnt;

// bf16 hi/lo split scratch for the tensor-core xW GEMM
__device__ __nv_bfloat16 g_xh[(size_t)SS * BB * II];   // 64 MB
__device__ __nv_bfloat16 g_xl[(size_t)SS * BB * II];
__device__ __nv_bfloat16 g_wh[(size_t)G4 * II];        // 8 MB
__device__ __nv_bfloat16 g_wl[(size_t)G4 * II];

__device__ __forceinline__ float sigf(float x) {
    return 1.0f / (1.0f + __expf(-x));
}
__device__ __forceinline__ float tanhfast(float x) {
    return fmaf(2.0f, sigf(2.0f * x), -1.0f);
}

typedef unsigned long long ull;

__device__ __forceinline__ void fma2(ull& d, ull a, ull b) {
    asm("fma.rn.f32x2 %0, %1, %2, %0;" : "+l"(d) : "l"(a), "l"(b));
}
__device__ __forceinline__ float2 u2f(ull v) {
    float2 r;
    asm("mov.b64 {%0, %1}, %2;" : "=f"(r.x), "=f"(r.y) : "l"(v));
    return r;
}

// ---------------- HMMA helpers (base-target ISA: sm_80+) ----------------
__device__ __forceinline__ uint32_t smem_u32(const void* p) {
    uint32_t a;
    asm("{ .reg .u64 t; cvta.to.shared.u64 t, %1; cvt.u32.u64 %0, t; }"
        : "=r"(a) : "l"(p));
    return a;
}
#define SW128(o) ((o) ^ (((o) >> 3) & 0x70))

__device__ __forceinline__ void hmma(float* c, const uint32_t* a, const uint32_t* b) {
    asm volatile(
        "mma.sync.aligned.m16n8k16.row.col.f32.bf16.bf16.f32 "
        "{%0,%1,%2,%3}, {%4,%5,%6,%7}, {%8,%9}, {%0,%1,%2,%3};"
        : "+f"(c[0]), "+f"(c[1]), "+f"(c[2]), "+f"(c[3])
        : "r"(a[0]), "r"(a[1]), "r"(a[2]), "r"(a[3]), "r"(b[0]), "r"(b[1]));
}
__device__ __forceinline__ void ldsm4(uint32_t* r, uint32_t addr) {
    asm volatile("ldmatrix.sync.aligned.m8n8.x4.shared.b16 {%0,%1,%2,%3}, [%4];"
        : "=r"(r[0]), "=r"(r[1]), "=r"(r[2]), "=r"(r[3]) : "r"(addr));
}
__device__ __forceinline__ void ldsm2(uint32_t* r, uint32_t addr) {
    asm volatile("ldmatrix.sync.aligned.m8n8.x2.shared.b16 {%0,%1}, [%2];"
        : "=r"(r[0]), "=r"(r[1]) : "r"(addr));
}
__device__ __forceinline__ void cpa16(uint32_t dst, const void* src) {
    asm volatile("cp.async.cg.shared.global [%0], [%1], 16;"
                 :: "r"(dst), "l"(src) : "memory");
}
#define CP_COMMIT() asm volatile("cp.async.commit_group;" ::: "memory")
#define CP_WAIT(n)  asm volatile("cp.async.wait_group %0;" :: "n"(n) : "memory")

// ---------------------------------------------------------------------------
// Split fp32 -> bf16 hi/lo
// ---------------------------------------------------------------------------
__device__ __forceinline__ void split4(float4 v, uint2& hi, uint2& lo) {
    __nv_bfloat16 h0 = __float2bfloat16(v.x), h1 = __float2bfloat16(v.y);
    __nv_bfloat16 h2 = __float2bfloat16(v.z), h3 = __float2bfloat16(v.w);
    __nv_bfloat16 l0 = __float2bfloat16(v.x - __bfloat162float(h0));
    __nv_bfloat16 l1 = __float2bfloat16(v.y - __bfloat162float(h1));
    __nv_bfloat16 l2 = __float2bfloat16(v.z - __bfloat162float(h2));
    __nv_bfloat16 l3 = __float2bfloat16(v.w - __bfloat162float(h3));
    __nv_bfloat162 ha(h0, h1), hb(h2, h3), la(l0, l1), lb(l2, l3);
    hi.x = *(uint32_t*)&ha; hi.y = *(uint32_t*)&hb;
    lo.x = *(uint32_t*)&la; lo.y = *(uint32_t*)&lb;
}

__global__ void cvt_x(const float* __restrict__ src) {
    const size_t i = (size_t)blockIdx.x * 256 + threadIdx.x;
    float4 v = *((const float4*)src + i);
    uint2 hi, lo;
    split4(v, hi, lo);
    ((uint2*)g_xh)[i] = hi;
    ((uint2*)g_xl)[i] = lo;
}

__global__ void cvt_w(const float* __restrict__ src) {
    const size_t i = (size_t)blockIdx.x * 256 + threadIdx.x;
    float4 v = *((const float4*)src + i);
    uint2 hi, lo;
    split4(v, hi, lo);
    ((uint2*)g_wh)[i] = hi;
    ((uint2*)g_wl)[i] = lo;
}

// ---------------------------------------------------------------------------
// Kernel A (HMMA): g_xw[m,g] = sum_i X[m,i]*W[g,i] + bias[g]
//   CTA: 128m x 128n. 8 warps (2m x 4n), warp = 64m x 32n.
//   K staged 64 at a time, cp.async double-buffered, SW128 smem.
//   3-term bf16 split: xh*wh + xh*wl + xl*wh, fp32 accum.
// ---------------------------------------------------------------------------
#define TCK 64
#define TERM 16384               // bytes per operand term per stage (128x64 bf16)
#define STAGEB 65536             // bytes per stage
#define NSTG (II / TCK)          // 16 stages

__global__ __launch_bounds__(256) void gemm_xw_hmma(const float* __restrict__ bias) {
    extern __shared__ __align__(1024) char dsm[];
    __shared__ float s_bias[128];

    const int tid = threadIdx.x;
    const int wid = tid >> 5;
    const int lid = tid & 31;
    const int wm = wid >> 2;          // 0..1 -> m offset 64*wm
    const int wn = wid & 3;           // 0..3 -> n offset 32*wn
    const int n0 = blockIdx.x << 7;
    const int m0 = blockIdx.y << 7;

    const uint32_t smbase = smem_u32(dsm);

    if (tid < 128) s_bias[tid] = bias[n0 + tid];

    // Loader mapping: idx = tid + j*256 -> row r = idx>>3, 16B chunk c = idx&7
    const __nv_bfloat16* xh = g_xh + (size_t)m0 * II;
    const __nv_bfloat16* xl = g_xl + (size_t)m0 * II;
    const __nv_bfloat16* wh = g_wh + (size_t)n0 * II;
    const __nv_bfloat16* wl = g_wl + (size_t)n0 * II;

    // Precompute per-thread loader offsets
    uint32_t s_off[4];
    size_t g_off[4];
    #pragma unroll
    for (int j = 0; j < 4; j++) {
        const int idx = tid + (j << 8);
        const int r = idx >> 3;
        const int c = idx & 7;
        s_off[j] = SW128((uint32_t)(r * 128 + c * 16));
        g_off[j] = (size_t)r * II + c * 8;
    }

    // ldmatrix addresses (fixed per thread; add stage base + chunk*16)
    //   A: rows wm*64 + mi*16 + (lid&15), chunk +(lid>>4)
    //   B: rows wn*32 + ni*8  + (lid&7),  chunk +((lid>>3)&1)
    uint32_t aRow[4], bRow[4];
    #pragma unroll
    for (int mi = 0; mi < 4; mi++)
        aRow[mi] = SW128((uint32_t)(((wm << 6) + (mi << 4) + (lid & 15)) * 128 +
                                    ((lid >> 4) << 4)));
    #pragma unroll
    for (int ni = 0; ni < 4; ni++)
        bRow[ni] = SW128((uint32_t)(((wn << 5) + (ni << 3) + (lid & 7)) * 128 +
                                    (((lid >> 3) & 1) << 4)));
    // NOTE: SW128 only permutes bits[6:4]; adding chunk*32 (bit5+) breaks the
    // XOR, so recompute per kc below instead of adding. Store raw rows too.
    uint32_t aRowRaw[4], bRowRaw[4];
    #pragma unroll
    for (int mi = 0; mi < 4; mi++)
        aRowRaw[mi] = (uint32_t)(((wm << 6) + (mi << 4) + (lid & 15)) * 128);
    #pragma unroll
    for (int ni = 0; ni < 4; ni++)
        bRowRaw[ni] = (uint32_t)(((wn << 5) + (ni << 3) + (lid & 7)) * 128);
    const uint32_t aChunk = (lid >> 4) << 4;           // 0 or 16
    const uint32_t bChunk = ((lid >> 3) & 1) << 4;     // 0 or 16
    (void)aRow; (void)bRow;

    float acc[4][4][4];
    #pragma unroll
    for (int mi = 0; mi < 4; mi++)
        #pragma unroll
        for (int ni = 0; ni < 4; ni++)
            #pragma unroll
            for (int q = 0; q < 4; q++) acc[mi][ni][q] = 0.0f;

    // Prologue: stage 0
    {
        const uint32_t sb = smbase;
        #pragma unroll
        for (int j = 0; j < 4; j++) {
            cpa16(sb + s_off[j],            xh + g_off[j]);
            cpa16(sb + TERM + s_off[j],     xl + g_off[j]);
            cpa16(sb + 2 * TERM + s_off[j], wh + g_off[j]);
            cpa16(sb + 3 * TERM + s_off[j], wl + g_off[j]);
        }
        CP_COMMIT();
    }

    for (int s = 0; s < NSTG; s++) {
        if (s + 1 < NSTG) {
            const uint32_t sb = smbase + ((s + 1) & 1) * STAGEB;
            const int k0 = (s + 1) * TCK;
            #pragma unroll
            for (int j = 0; j < 4; j++) {
                cpa16(sb + s_off[j],            xh + g_off[j] + k0);
                cpa16(sb + TERM + s_off[j],     xl + g_off[j] + k0);
                cpa16(sb + 2 * TERM + s_off[j], wh + g_off[j] + k0);
                cpa16(sb + 3 * TERM + s_off[j], wl + g_off[j] + k0);
            }
            CP_COMMIT();
            CP_WAIT(1);
        } else {
            CP_WAIT(0);
        }
        __syncthreads();

        const uint32_t sb = smbase + (s & 1) * STAGEB;
        #pragma unroll
        for (int kc = 0; kc < 4; kc++) {
            uint32_t ah[4][4], al[4][4], bh[4][2], bl[4][2];
            #pragma unroll
            for (int mi = 0; mi < 4; mi++) {
                const uint32_t ao = SW128(aRowRaw[mi] + (kc << 5) + aChunk);
                ldsm4(ah[mi], sb + ao);
                ldsm4(al[mi], sb + TERM + ao);
            }
            #pragma unroll
            for (int ni = 0; ni < 4; ni++) {
                const uint32_t bo = SW128(bRowRaw[ni] + (kc << 5) + bChunk);
                ldsm2(bh[ni], sb + 2 * TERM + bo);
                ldsm2(bl[ni], sb + 3 * TERM + bo);
            }
            #pragma unroll
            for (int mi = 0; mi < 4; mi++)
                #pragma unroll
                for (int ni = 0; ni < 4; ni++) {
                    hmma(acc[mi][ni], ah[mi], bh[ni]);
                    hmma(acc[mi][ni], ah[mi], bl[ni]);
                    hmma(acc[mi][ni], al[mi], bh[ni]);
                }
        }
        __syncthreads();
    }

    // Epilogue: bias add + store
    #pragma unroll
    for (int mi = 0; mi < 4; mi++) {
        const int mA = m0 + (wm << 6) + (mi << 4) + (lid >> 2);
        #pragma unroll
        for (int ni = 0; ni < 4; ni++) {
            const int colB = (wn << 5) + (ni << 3) + ((lid & 3) << 1);
            const float b0 = s_bias[colB], b1 = s_bias[colB + 1];
            float2 o0 = {acc[mi][ni][0] + b0, acc[mi][ni][1] + b1};
            float2 o1 = {acc[mi][ni][2] + b0, acc[mi][ni][3] + b1};
            *(float2*)(g_xw + (size_t)mA * G4 + n0 + colB)       = o0;
            *(float2*)(g_xw + (size_t)(mA + 8) * G4 + n0 + colB) = o1;
        }
    }
}

// ---------------------------------------------------------------------------
// Kernel B: PERSISTENT LSTM — unchanged from the R9 winner.
// ---------------------------------------------------------------------------
__global__ __launch_bounds__(256) void lstm_persist(const float* __restrict__ h0,
                                                    const float* __restrict__ U,
                                                    float* __restrict__ out) {
    __shared__ __align__(16) float Ad[BKS][140];
    __shared__ __align__(16) float Bs[BKS][264];

    const int bid = blockIdx.x;
    const int nb = bid >> 3;
    const int kb = bid & 7;
    const int kbase = kb * BKC;
    const int tid = threadIdx.x;
    const int tx = tid & 31;
    const int ty = tid >> 5;

    const int ar = tid >> 2;
    const int ak = (tid & 3) << 2;

    const int ur = tid >> 2;
    const int uk = (tid & 3) << 2;
    const float* uP = U + (size_t)((nb << 6) + ur) * HH + kbase + uk;
    const size_t ugstr = (size_t)1024 * HH;

    const int gidxA = ((tx >> 4) << 10) + (nb << 6) + ((tx & 15) << 2);

    const int cb  = tid >> 2;
    const int hcol = (nb << 6) + (kb << 3) + ((tid & 3) << 1);

    for (int t = 0; t < SS; t++) {
        const float* hprev = t ? (out + (size_t)(t - 1) * BHH) : h0;
        const int par = t & 1;

        const float* aP = hprev + (size_t)ar * HH + kbase + ak;

        float4 ha  = *(const float4*)(aP);
        float4 ub0 = *(const float4*)(uP);
        float4 ub1 = *(const float4*)(uP + ugstr);
        float4 ub2 = *(const float4*)(uP + 2 * ugstr);
        float4 ub3 = *(const float4*)(uP + 3 * ugstr);

        ull acc[8][4];
        #pragma unroll
        for (int i = 0; i < 8; i++)
            #pragma unroll
            for (int j = 0; j < 4; j++) acc[i][j] = 0ull;

        for (int s = 0; s < BKC; s += BKS) {
            #pragma unroll
            for (int i = 0; i < 4; i++) {
                const float av = (&ha.x)[i];
                Ad[ak + i][2 * ar]     = av;
                Ad[ak + i][2 * ar + 1] = av;
                Bs[uk + i][ur]       = (&ub0.x)[i];
                Bs[uk + i][ur + 64]  = (&ub1.x)[i];
                Bs[uk + i][ur + 128] = (&ub2.x)[i];
                Bs[uk + i][ur + 192] = (&ub3.x)[i];
            }
            __syncthreads();

            if (s + BKS < BKC) {
                ha  = *(const float4*)(aP + s + BKS);
                ub0 = *(const float4*)(uP + s + BKS);
                ub1 = *(const float4*)(uP + ugstr + s + BKS);
                ub2 = *(const float4*)(uP + 2 * ugstr + s + BKS);
                ub3 = *(const float4*)(uP + 3 * ugstr + s + BKS);
            }

            #pragma unroll
            for (int k = 0; k < BKS; k++) {
                ull a2[8];
                #pragma unroll
                for (int i2 = 0; i2 < 4; i2++) {
                    const ulonglong2 aa =
                        *(const ulonglong2*)&Ad[k][(ty << 4) + (i2 << 2)];
                    a2[2 * i2]     = aa.x;
                    a2[2 * i2 + 1] = aa.y;
                }
                const ulonglong2 bb0 = *(const ulonglong2*)&Bs[k][tx << 2];
                const ulonglong2 bb1 = *(const ulonglong2*)&Bs[k][128 + (tx << 2)];
                ull b2[4] = {bb0.x, bb0.y, bb1.x, bb1.y};

                #pragma unroll
                for (int i = 0; i < 8; i++) {
                    fma2(acc[i][0], a2[i], b2[0]);
                    fma2(acc[i][1], a2[i], b2[1]);
                    fma2(acc[i][2], a2[i], b2[2]);
                    fma2(acc[i][3], a2[i], b2[3]);
                }
            }
            __syncthreads();
        }

        {
            float* pout = g_part[kb];
            #pragma unroll
            for (int i = 0; i < 8; i++) {
                const int m = (ty << 3) + i;
                const float2 p0 = u2f(acc[i][0]);
                const float2 p1 = u2f(acc[i][1]);
                const float2 p2 = u2f(acc[i][2]);
                const float2 p3 = u2f(acc[i][3]);
                float4 oA = {p0.x, p0.y, p1.x, p1.y};
                float4 oB = {p2.x, p2.y, p3.x, p3.y};
                *(float4*)(pout + (size_t)m * G4 + gidxA)        = oA;
                *(float4*)(pout + (size_t)m * G4 + gidxA + 2048) = oB;
            }
        }

        __threadfence();
        __syncthreads();
        if (tid == 0) {
            atomicAdd(&g_nbcnt[nb], 1u);
            while (atomicAdd(&g_nbcnt[nb], 0u) < 8u * (unsigned)(t + 1)) {
                __nanosleep(32);
            }
        }
        __syncthreads();

        {
            float2 gate[4];
            #pragma unroll
            for (int g = 0; g < 4; g++) {
                const size_t off = (size_t)cb * G4 + (g << 10) + hcol;
                float2 s = *(const float2*)(g_xw + (size_t)t * BB * G4 + off);
                #pragma unroll
                for (int p = 0; p < NKB; p++) {
                    const float2 pv = __ldcg((const float2*)(g_part[p] + off));
                    s.x += pv.x; s.y += pv.y;
                }
                gate[g] = s;
            }

            const int idx = cb * HH + hcol;
            const float2 cp = *(const float2*)(g_c[par] + idx);
            float2 cn, hv;
            {
                const float iv = sigf(gate[0].x), fv = sigf(gate[1].x);
                const float gv = tanhfast(gate[2].x), ov = sigf(gate[3].x);
                cn.x = fv * cp.x + iv * gv;  hv.x = ov * tanhfast(cn.x);
            }
            {
                const float iv = sigf(gate[0].y), fv = sigf(gate[1].y);
                const float gv = tanhfast(gate[2].y), ov = sigf(gate[3].y);
                cn.y = fv * cp.y + iv * gv;  hv.y = ov * tanhfast(cn.y);
            }
            *(float2*)(g_c[par ^ 1] + idx) = cn;
            *(float2*)(out + (size_t)t * BHH + idx) = hv;
        }

        __threadfence();
        __syncthreads();
        if (tid == 0) {
            atomicAdd(&g_stepcnt, 1u);
            if (t + 1 < SS) {
                while (atomicAdd(&g_stepcnt, 0u) < 128u * (unsigned)(t + 1)) {
                    __nanosleep(32);
                }
            }
        }
        __syncthreads();
    }
}

// ---------------------------------------------------------------------------
// Helpers
// ---------------------------------------------------------------------------
__global__ void copy_c0(const float* __restrict__ c0) {
    const int i = blockIdx.x * 256 + threadIdx.x;
    g_c[0][i] = c0[i];
    if (blockIdx.x == 0) {
        if (threadIdx.x < NNB) g_nbcnt[threadIdx.x] = 0u;
        if (threadIdx.x == NNB) g_stepcnt = 0u;
    }
}

__global__ void finalize(float* __restrict__ out) {
    const int i = blockIdx.x * 256 + threadIdx.x;
    const size_t base = (size_t)SS * BHH;
    out[base + i] = out[(size_t)(SS - 1) * BHH + i];   // h_t
    out[base + BHH + i] = g_c[0][i];                   // c_t (S even)
}

// ---------------------------------------------------------------------------
extern "C" void kernel_launch(void* const* d_in, const int* in_sizes, int n_in,
                              void* d_out, int out_size) {
    (void)in_sizes; (void)n_in; (void)out_size;
    const float* x  = (const float*)d_in[0];
    const float* h0 = (const float*)d_in[1];
    const float* c0 = (const float*)d_in[2];
    const float* Ww = (const float*)d_in[3];
    const float* Wb = (const float*)d_in[4];
    const float* Uw = (const float*)d_in[5];
    float* out = (float*)d_out;

    cudaFuncSetAttribute(gemm_xw_hmma,
                         cudaFuncAttributeMaxDynamicSharedMemorySize,
                         2 * STAGEB);

    copy_c0<<<(BB * HH) / 256, 256>>>(c0);

    cvt_x<<<(SS * BB * II / 4) / 256, 256>>>(x);
    cvt_w<<<(G4 * II / 4) / 256, 256>>>(Ww);

    gemm_xw_hmma<<<dim3(G4 / 128, (SS * BB) / 128), 256, 2 * STAGEB>>>(Wb);

    lstm_persist<<<NNB * NKB, 256>>>(h0, Uw, out);

    finalize<<<(BB * HH) / 256, 256>>>(out);
}

// round 12
// speedup vs baseline: 2.4123x; 1.6462x over previous
#include <cuda_runtime.h>
#include <cuda_bf16.h>
#include <math.h>
#include <stdint.h>

#define SS 512
#define BB 64
#define II 1024
#define HH 1024
#define G4 4096   // 4*H
#define BHH (BB * HH)

#define NKB 8          // K-split factor for the step GEMM
#define NNB 16         // n-blocks (gate-coherent, 64 h-cols each)
#define BKC 128        // k-span per step block

// Scratch
__device__ float g_xw[(size_t)SS * BB * G4];       // 512 MB
__device__ float g_part[NKB][BB * G4];             // 8 MB
__device__ float g_c[2][BHH];
__device__ unsigned g_nbcnt[NNB];
__device__ unsigned g_stepcnt;

// bf16 hi/lo splits
__device__ __nv_bfloat16 g_xh[(size_t)SS * BB * II];   // 64 MB
__device__ __nv_bfloat16 g_xl[(size_t)SS * BB * II];
__device__ __nv_bfloat16 g_wh[(size_t)G4 * II];        // 8 MB
__device__ __nv_bfloat16 g_wl[(size_t)G4 * II];
__device__ __nv_bfloat16 g_uh[(size_t)G4 * HH];        // 8 MB
__device__ __nv_bfloat16 g_ul[(size_t)G4 * HH];
__device__ __nv_bfloat16 g_hh[BHH];                    // 128 KB
__device__ __nv_bfloat16 g_hl[BHH];

__device__ __forceinline__ float sigf(float x) {
    return 1.0f / (1.0f + __expf(-x));
}
__device__ __forceinline__ float tanhfast(float x) {
    return fmaf(2.0f, sigf(2.0f * x), -1.0f);
}

// ---------------- HMMA helpers (base-target ISA: sm_80+) ----------------
__device__ __forceinline__ uint32_t smem_u32(const void* p) {
    uint32_t a;
    asm("{ .reg .u64 t; cvta.to.shared.u64 t, %1; cvt.u32.u64 %0, t; }"
        : "=r"(a) : "l"(p));
    return a;
}
#define SW128(o) ((o) ^ (((o) >> 3) & 0x70))

__device__ __forceinline__ void hmma(float* c, const uint32_t* a, const uint32_t* b) {
    asm volatile(
        "mma.sync.aligned.m16n8k16.row.col.f32.bf16.bf16.f32 "
        "{%0,%1,%2,%3}, {%4,%5,%6,%7}, {%8,%9}, {%0,%1,%2,%3};"
        : "+f"(c[0]), "+f"(c[1]), "+f"(c[2]), "+f"(c[3])
        : "r"(a[0]), "r"(a[1]), "r"(a[2]), "r"(a[3]), "r"(b[0]), "r"(b[1]));
}
__device__ __forceinline__ void ldsm4(uint32_t* r, uint32_t addr) {
    asm volatile("ldmatrix.sync.aligned.m8n8.x4.shared.b16 {%0,%1,%2,%3}, [%4];"
        : "=r"(r[0]), "=r"(r[1]), "=r"(r[2]), "=r"(r[3]) : "r"(addr));
}
__device__ __forceinline__ void ldsm2(uint32_t* r, uint32_t addr) {
    asm volatile("ldmatrix.sync.aligned.m8n8.x2.shared.b16 {%0,%1}, [%2];"
        : "=r"(r[0]), "=r"(r[1]) : "r"(addr));
}
__device__ __forceinline__ void cpa16(uint32_t dst, const void* src) {
    asm volatile("cp.async.cg.shared.global [%0], [%1], 16;"
                 :: "r"(dst), "l"(src) : "memory");
}
__device__ __forceinline__ void cpa16_ca(uint32_t dst, const void* src) {
    asm volatile("cp.async.ca.shared.global [%0], [%1], 16;"
                 :: "r"(dst), "l"(src) : "memory");
}
#define CP_COMMIT() asm volatile("cp.async.commit_group;" ::: "memory")
#define CP_WAIT(n)  asm volatile("cp.async.wait_group %0;" :: "n"(n) : "memory")

// ---------------------------------------------------------------------------
// Split fp32 -> bf16 hi/lo (generic)
// ---------------------------------------------------------------------------
__device__ __forceinline__ void split4(float4 v, uint2& hi, uint2& lo) {
    __nv_bfloat16 h0 = __float2bfloat16(v.x), h1 = __float2bfloat16(v.y);
    __nv_bfloat16 h2 = __float2bfloat16(v.z), h3 = __float2bfloat16(v.w);
    __nv_bfloat16 l0 = __float2bfloat16(v.x - __bfloat162float(h0));
    __nv_bfloat16 l1 = __float2bfloat16(v.y - __bfloat162float(h1));
    __nv_bfloat16 l2 = __float2bfloat16(v.z - __bfloat162float(h2));
    __nv_bfloat16 l3 = __float2bfloat16(v.w - __bfloat162float(h3));
    __nv_bfloat162 ha(h0, h1), hb(h2, h3), la(l0, l1), lb(l2, l3);
    hi.x = *(uint32_t*)&ha; hi.y = *(uint32_t*)&hb;
    lo.x = *(uint32_t*)&la; lo.y = *(uint32_t*)&lb;
}

__global__ void cvt_split(const float* __restrict__ src,
                          __nv_bfloat16* __restrict__ dhi,
                          __nv_bfloat16* __restrict__ dlo) {
    const size_t i = (size_t)blockIdx.x * 256 + threadIdx.x;
    float4 v = *((const float4*)src + i);
    uint2 hi, lo;
    split4(v, hi, lo);
    ((uint2*)dhi)[i] = hi;
    ((uint2*)dlo)[i] = lo;
}

// ---------------------------------------------------------------------------
// Kernel A (HMMA): g_xw[m,g] = sum_i X[m,i]*W[g,i] + bias[g]  (R11 winner)
// ---------------------------------------------------------------------------
#define TCK 64
#define TERM 16384
#define STAGEB 65536
#define NSTG (II / TCK)

__global__ __launch_bounds__(256) void gemm_xw_hmma(const float* __restrict__ bias) {
    extern __shared__ __align__(1024) char dsm[];
    __shared__ float s_bias[128];

    const int tid = threadIdx.x;
    const int wid = tid >> 5;
    const int lid = tid & 31;
    const int wm = wid >> 2;
    const int wn = wid & 3;
    const int n0 = blockIdx.x << 7;
    const int m0 = blockIdx.y << 7;

    const uint32_t smbase = smem_u32(dsm);

    if (tid < 128) s_bias[tid] = bias[n0 + tid];

    const __nv_bfloat16* xh = g_xh + (size_t)m0 * II;
    const __nv_bfloat16* xl = g_xl + (size_t)m0 * II;
    const __nv_bfloat16* wh = g_wh + (size_t)n0 * II;
    const __nv_bfloat16* wl = g_wl + (size_t)n0 * II;

    uint32_t s_off[4];
    size_t g_off[4];
    #pragma unroll
    for (int j = 0; j < 4; j++) {
        const int idx = tid + (j << 8);
        const int r = idx >> 3;
        const int c = idx & 7;
        s_off[j] = SW128((uint32_t)(r * 128 + c * 16));
        g_off[j] = (size_t)r * II + c * 8;
    }

    uint32_t aRowRaw[4], bRowRaw[4];
    #pragma unroll
    for (int mi = 0; mi < 4; mi++)
        aRowRaw[mi] = (uint32_t)(((wm << 6) + (mi << 4) + (lid & 15)) * 128);
    #pragma unroll
    for (int ni = 0; ni < 4; ni++)
        bRowRaw[ni] = (uint32_t)(((wn << 5) + (ni << 3) + (lid & 7)) * 128);
    const uint32_t aChunk = (lid >> 4) << 4;
    const uint32_t bChunk = ((lid >> 3) & 1) << 4;

    float acc[4][4][4];
    #pragma unroll
    for (int mi = 0; mi < 4; mi++)
        #pragma unroll
        for (int ni = 0; ni < 4; ni++)
            #pragma unroll
            for (int q = 0; q < 4; q++) acc[mi][ni][q] = 0.0f;

    {
        const uint32_t sb = smbase;
        #pragma unroll
        for (int j = 0; j < 4; j++) {
            cpa16(sb + s_off[j],            xh + g_off[j]);
            cpa16(sb + TERM + s_off[j],     xl + g_off[j]);
            cpa16(sb + 2 * TERM + s_off[j], wh + g_off[j]);
            cpa16(sb + 3 * TERM + s_off[j], wl + g_off[j]);
        }
        CP_COMMIT();
    }

    for (int s = 0; s < NSTG; s++) {
        if (s + 1 < NSTG) {
            const uint32_t sb = smbase + ((s + 1) & 1) * STAGEB;
            const int k0 = (s + 1) * TCK;
            #pragma unroll
            for (int j = 0; j < 4; j++) {
                cpa16(sb + s_off[j],            xh + g_off[j] + k0);
                cpa16(sb + TERM + s_off[j],     xl + g_off[j] + k0);
                cpa16(sb + 2 * TERM + s_off[j], wh + g_off[j] + k0);
                cpa16(sb + 3 * TERM + s_off[j], wl + g_off[j] + k0);
            }
            CP_COMMIT();
            CP_WAIT(1);
        } else {
            CP_WAIT(0);
        }
        __syncthreads();

        const uint32_t sb = smbase + (s & 1) * STAGEB;
        #pragma unroll
        for (int kc = 0; kc < 4; kc++) {
            uint32_t ah[4][4], al[4][4], bh[4][2], bl[4][2];
            #pragma unroll
            for (int mi = 0; mi < 4; mi++) {
                const uint32_t ao = SW128(aRowRaw[mi] + (kc << 5) + aChunk);
                ldsm4(ah[mi], sb + ao);
                ldsm4(al[mi], sb + TERM + ao);
            }
            #pragma unroll
            for (int ni = 0; ni < 4; ni++) {
                const uint32_t bo = SW128(bRowRaw[ni] + (kc << 5) + bChunk);
                ldsm2(bh[ni], sb + 2 * TERM + bo);
                ldsm2(bl[ni], sb + 3 * TERM + bo);
            }
            #pragma unroll
            for (int mi = 0; mi < 4; mi++)
                #pragma unroll
                for (int ni = 0; ni < 4; ni++) {
                    hmma(acc[mi][ni], ah[mi], bh[ni]);
                    hmma(acc[mi][ni], ah[mi], bl[ni]);
                    hmma(acc[mi][ni], al[mi], bh[ni]);
                }
        }
        __syncthreads();
    }

    #pragma unroll
    for (int mi = 0; mi < 4; mi++) {
        const int mA = m0 + (wm << 6) + (mi << 4) + (lid >> 2);
        #pragma unroll
        for (int ni = 0; ni < 4; ni++) {
            const int colB = (wn << 5) + (ni << 3) + ((lid & 3) << 1);
            const float b0 = s_bias[colB], b1 = s_bias[colB + 1];
            float2 o0 = {acc[mi][ni][0] + b0, acc[mi][ni][1] + b1};
            float2 o1 = {acc[mi][ni][2] + b0, acc[mi][ni][3] + b1};
            *(float2*)(g_xw + (size_t)mA * G4 + n0 + colB)       = o0;
            *(float2*)(g_xw + (size_t)(mA + 8) * G4 + n0 + colB) = o1;
        }
    }
}

// ---------------------------------------------------------------------------
// Kernel B: PERSISTENT LSTM with HMMA phase-1.
//   128 blocks (nb=bid>>3, kb=bid&7), 256 threads, single wave.
//   Per step:
//     Load A = h_{hi,lo}[64 x 128k] (cp.async.cg, L1-bypassed: addresses are
//       rewritten each step by other SMs) and B = U_{hi,lo}[256 x 128k]
//       (cp.async.ca, read-only) into 160 KB SMEM (SW128, 64k atoms).
//     3-term HMMA 64m x 256n x 128k -> fp32 partials -> g_part[kb].
//     nb-group counter sync; combine 8 h-cols/block: sum partials (__ldcg)
//       + xW, gates, c update, write h fp32 to out AND bf16 hi/lo to g_hh/g_hl.
//     Grid barrier via monotonic counter.
// ---------------------------------------------------------------------------
#define A_HI 0
#define A_LO 16384
#define B_HI 32768
#define B_LO 98304
#define SMEMB 163840
#define A_ATOM 8192     // 64 rows * 128B
#define B_ATOM 32768    // 256 rows * 128B

__global__ __launch_bounds__(256) void lstm_persist_tc(float* __restrict__ out) {
    extern __shared__ __align__(1024) char dsm[];

    const int bid = blockIdx.x;
    const int nb = bid >> 3;              // 0..15
    const int kb = bid & 7;               // 0..7
    const int tid = threadIdx.x;
    const int wid = tid >> 5;             // warp = n-slab of 32 cols
    const int lid = tid & 31;

    const uint32_t smbase = smem_u32(dsm);

    // ---- loader precompute ----
    // A: 1024 16B-chunks per term. idx -> r=idx>>4 (batch), c=idx&15 (k chunk)
    uint32_t aso[4];
    size_t   ago[4];
    #pragma unroll
    for (int j = 0; j < 4; j++) {
        const int idx = tid + (j << 8);
        const int r = idx >> 4, c = idx & 15;
        aso[j] = (uint32_t)((c >> 3) * A_ATOM) +
                 SW128((uint32_t)(r * 128 + (c & 7) * 16));
        ago[j] = (size_t)r * HH + kb * BKC + c * 8;
    }
    // B: 4096 chunks per term. r = local n row (0..255) -> global U row G(r)
    uint32_t bso[16];
    size_t   bgo[16];
    #pragma unroll
    for (int j = 0; j < 16; j++) {
        const int idx = tid + (j << 8);
        const int r = idx >> 4, c = idx & 15;
        const int G = ((r >> 6) << 10) + (nb << 6) + (r & 63);
        bso[j] = (uint32_t)((c >> 3) * B_ATOM) +
                 SW128((uint32_t)(r * 128 + (c & 7) * 16));
        bgo[j] = (size_t)G * HH + kb * BKC + c * 8;
    }

    // ldmatrix row bases
    uint32_t aRowRaw[4], bRowRaw[4];
    #pragma unroll
    for (int mi = 0; mi < 4; mi++)
        aRowRaw[mi] = (uint32_t)(((mi << 4) + (lid & 15)) * 128);
    #pragma unroll
    for (int ni = 0; ni < 4; ni++)
        bRowRaw[ni] = (uint32_t)(((wid << 5) + (ni << 3) + (lid & 7)) * 128);
    const uint32_t aChunk = (lid >> 4) << 4;
    const uint32_t bChunk = ((lid >> 3) & 1) << 4;

    // combine indices (same as R9): 8 h-cols per block
    const int cb  = tid >> 2;
    const int hcol = (nb << 6) + (kb << 3) + ((tid & 3) << 1);

    for (int t = 0; t < SS; t++) {
        const int par = t & 1;

        // ---------------- load A and B tiles ----------------
        #pragma unroll
        for (int j = 0; j < 4; j++) {
            cpa16(smbase + A_HI + aso[j], g_hh + ago[j]);
            cpa16(smbase + A_LO + aso[j], g_hl + ago[j]);
        }
        #pragma unroll
        for (int j = 0; j < 16; j++) {
            cpa16_ca(smbase + B_HI + bso[j], g_uh + bgo[j]);
            cpa16_ca(smbase + B_LO + bso[j], g_ul + bgo[j]);
        }
        CP_COMMIT();
        CP_WAIT(0);
        __syncthreads();

        // ---------------- HMMA: 64m x 256n x 128k, 3 terms ----------------
        float acc[4][4][4];
        #pragma unroll
        for (int mi = 0; mi < 4; mi++)
            #pragma unroll
            for (int ni = 0; ni < 4; ni++)
                #pragma unroll
                for (int q = 0; q < 4; q++) acc[mi][ni][q] = 0.0f;

        #pragma unroll
        for (int kk = 0; kk < 8; kk++) {
            const uint32_t aAt = (uint32_t)((kk >> 2) * A_ATOM);
            const uint32_t bAt = (uint32_t)((kk >> 2) * B_ATOM);
            const uint32_t kco = (uint32_t)((kk & 3) << 5);

            uint32_t ah[4][4], al[4][4], bh[4][2], bl[4][2];
            #pragma unroll
            for (int mi = 0; mi < 4; mi++) {
                const uint32_t ao = aAt + SW128(aRowRaw[mi] + kco + aChunk);
                ldsm4(ah[mi], smbase + A_HI + ao);
                ldsm4(al[mi], smbase + A_LO + ao);
            }
            #pragma unroll
            for (int ni = 0; ni < 4; ni++) {
                const uint32_t bo = bAt + SW128(bRowRaw[ni] + kco + bChunk);
                ldsm2(bh[ni], smbase + B_HI + bo);
                ldsm2(bl[ni], smbase + B_LO + bo);
            }
            #pragma unroll
            for (int mi = 0; mi < 4; mi++)
                #pragma unroll
                for (int ni = 0; ni < 4; ni++) {
                    hmma(acc[mi][ni], ah[mi], bh[ni]);
                    hmma(acc[mi][ni], ah[mi], bl[ni]);
                    hmma(acc[mi][ni], al[mi], bh[ni]);
                }
        }

        // ---------------- store partials ----------------
        {
            float* pout = g_part[kb];
            #pragma unroll
            for (int mi = 0; mi < 4; mi++) {
                const int m = (mi << 4) + (lid >> 2);
                #pragma unroll
                for (int ni = 0; ni < 4; ni++) {
                    const int c = (wid << 5) + (ni << 3) + ((lid & 3) << 1);
                    const int G = ((c >> 6) << 10) + (nb << 6) + (c & 63);
                    float2 o0 = {acc[mi][ni][0], acc[mi][ni][1]};
                    float2 o1 = {acc[mi][ni][2], acc[mi][ni][3]};
                    *(float2*)(pout + (size_t)m * G4 + G)       = o0;
                    *(float2*)(pout + (size_t)(m + 8) * G4 + G) = o1;
                }
            }
        }

        // ---------------- nb-group sync ----------------
        __threadfence();
        __syncthreads();
        if (tid == 0) {
            atomicAdd(&g_nbcnt[nb], 1u);
            while (atomicAdd(&g_nbcnt[nb], 0u) < 8u * (unsigned)(t + 1)) {
                __nanosleep(32);
            }
        }
        __syncthreads();

        // ---------------- combine + elementwise ----------------
        {
            float2 gate[4];
            #pragma unroll
            for (int g = 0; g < 4; g++) {
                const size_t off = (size_t)cb * G4 + (g << 10) + hcol;
                float2 s = *(const float2*)(g_xw + (size_t)t * BB * G4 + off);
                #pragma unroll
                for (int p = 0; p < NKB; p++) {
                    const float2 pv = __ldcg((const float2*)(g_part[p] + off));
                    s.x += pv.x; s.y += pv.y;
                }
                gate[g] = s;
            }

            const int idx = cb * HH + hcol;
            const float2 cp = *(const float2*)(g_c[par] + idx);
            float2 cn, hv;
            {
                const float iv = sigf(gate[0].x), fv = sigf(gate[1].x);
                const float gv = tanhfast(gate[2].x), ov = sigf(gate[3].x);
                cn.x = fv * cp.x + iv * gv;  hv.x = ov * tanhfast(cn.x);
            }
            {
                const float iv = sigf(gate[0].y), fv = sigf(gate[1].y);
                const float gv = tanhfast(gate[2].y), ov = sigf(gate[3].y);
                cn.y = fv * cp.y + iv * gv;  hv.y = ov * tanhfast(cn.y);
            }
            *(float2*)(g_c[par ^ 1] + idx) = cn;
            *(float2*)(out + (size_t)t * BHH + idx) = hv;

            // bf16 hi/lo split of h for the next step's MMA
            __nv_bfloat16 h0b = __float2bfloat16(hv.x);
            __nv_bfloat16 h1b = __float2bfloat16(hv.y);
            __nv_bfloat16 l0b = __float2bfloat16(hv.x - __bfloat162float(h0b));
            __nv_bfloat16 l1b = __float2bfloat16(hv.y - __bfloat162float(h1b));
            __nv_bfloat162 hp(h0b, h1b), lp(l0b, l1b);
            *(__nv_bfloat162*)(g_hh + idx) = hp;
            *(__nv_bfloat162*)(g_hl + idx) = lp;
        }

        // ---------------- grid step barrier ----------------
        __threadfence();
        __syncthreads();
        if (tid == 0) {
            atomicAdd(&g_stepcnt, 1u);
            if (t + 1 < SS) {
                while (atomicAdd(&g_stepcnt, 0u) < 128u * (unsigned)(t + 1)) {
                    __nanosleep(32);
                }
            }
        }
        __syncthreads();
    }
}

// ---------------------------------------------------------------------------
// Helpers
// ---------------------------------------------------------------------------
__global__ void seed_state(const float* __restrict__ c0,
                           const float* __restrict__ h0) {
    const int i = blockIdx.x * 256 + threadIdx.x;
    g_c[0][i] = c0[i];
    const float h = h0[i];
    const __nv_bfloat16 hh = __float2bfloat16(h);
    g_hh[i] = hh;
    g_hl[i] = __float2bfloat16(h - __bfloat162float(hh));
    if (blockIdx.x == 0) {
        if (threadIdx.x < NNB) g_nbcnt[threadIdx.x] = 0u;
        if (threadIdx.x == NNB) g_stepcnt = 0u;
    }
}

__global__ void finalize(float* __restrict__ out) {
    const int i = blockIdx.x * 256 + threadIdx.x;
    const size_t base = (size_t)SS * BHH;
    out[base + i] = out[(size_t)(SS - 1) * BHH + i];   // h_t
    out[base + BHH + i] = g_c[0][i];                   // c_t (S even)
}

// ---------------------------------------------------------------------------
extern "C" void kernel_launch(void* const* d_in, const int* in_sizes, int n_in,
                              void* d_out, int out_size) {
    (void)in_sizes; (void)n_in; (void)out_size;
    const float* x  = (const float*)d_in[0];
    const float* h0 = (const float*)d_in[1];
    const float* c0 = (const float*)d_in[2];
    const float* Ww = (const float*)d_in[3];
    const float* Wb = (const float*)d_in[4];
    const float* Uw = (const float*)d_in[5];
    float* out = (float*)d_out;

    cudaFuncSetAttribute(gemm_xw_hmma,
                         cudaFuncAttributeMaxDynamicSharedMemorySize,
                         2 * STAGEB);
    cudaFuncSetAttribute(lstm_persist_tc,
                         cudaFuncAttributeMaxDynamicSharedMemorySize,
                         SMEMB);

    seed_state<<<BHH / 256, 256>>>(c0, h0);

    __nv_bfloat16 *xh, *xl, *wh, *wl, *uh, *ul;
    cudaGetSymbolAddress((void**)&xh, g_xh);
    cudaGetSymbolAddress((void**)&xl, g_xl);
    cudaGetSymbolAddress((void**)&wh, g_wh);
    cudaGetSymbolAddress((void**)&wl, g_wl);
    cudaGetSymbolAddress((void**)&uh, g_uh);
    cudaGetSymbolAddress((void**)&ul, g_ul);

    cvt_split<<<(SS * BB * II / 4) / 256, 256>>>(x, xh, xl);
    cvt_split<<<(G4 * II / 4) / 256, 256>>>(Ww, wh, wl);
    cvt_split<<<(G4 * HH / 4) / 256, 256>>>(Uw, uh, ul);

    gemm_xw_hmma<<<dim3(G4 / 128, (SS * BB) / 128), 256, 2 * STAGEB>>>(Wb);

    lstm_persist_tc<<<NNB * NKB, 256, SMEMB>>>(out);

    finalize<<<BHH / 256, 256>>>(out);
}

// round 13
// speedup vs baseline: 2.5115x; 1.0411x over previous
#include <cuda_runtime.h>
#include <cuda_bf16.h>
#include <math.h>
#include <stdint.h>

#define SS 512
#define BB 64
#define II 1024
#define HH 1024
#define G4 4096   // 4*H
#define BHH (BB * HH)

#define NKB 8          // K-split factor for the step GEMM
#define NNB 16         // n-blocks (gate-coherent, 64 h-cols each)
#define BKC 128        // k-span per step block

// Scratch
__device__ float g_xw[(size_t)SS * BB * G4];       // 512 MB
__device__ float g_part[NKB][BB * G4];             // 8 MB
__device__ float g_c[2][BHH];
__device__ unsigned g_nbcnt[NNB];
__device__ unsigned g_stepcnt;

// bf16 hi/lo splits
__device__ __nv_bfloat16 g_xh[(size_t)SS * BB * II];   // 64 MB
__device__ __nv_bfloat16 g_xl[(size_t)SS * BB * II];
__device__ __nv_bfloat16 g_wh[(size_t)G4 * II];        // 8 MB
__device__ __nv_bfloat16 g_wl[(size_t)G4 * II];
__device__ __nv_bfloat16 g_uh[(size_t)G4 * HH];        // 8 MB
__device__ __nv_bfloat16 g_ul[(size_t)G4 * HH];
__device__ __nv_bfloat16 g_hh[BHH];                    // 128 KB
__device__ __nv_bfloat16 g_hl[BHH];

__device__ __forceinline__ float sigf(float x) {
    return 1.0f / (1.0f + __expf(-x));
}
__device__ __forceinline__ float tanhfast(float x) {
    return fmaf(2.0f, sigf(2.0f * x), -1.0f);
}

// ---------------- HMMA helpers (base-target ISA: sm_80+) ----------------
__device__ __forceinline__ uint32_t smem_u32(const void* p) {
    uint32_t a;
    asm("{ .reg .u64 t; cvta.to.shared.u64 t, %1; cvt.u32.u64 %0, t; }"
        : "=r"(a) : "l"(p));
    return a;
}
#define SW128(o) ((o) ^ (((o) >> 3) & 0x70))

__device__ __forceinline__ void hmma(float* c, const uint32_t* a, const uint32_t* b) {
    asm volatile(
        "mma.sync.aligned.m16n8k16.row.col.f32.bf16.bf16.f32 "
        "{%0,%1,%2,%3}, {%4,%5,%6,%7}, {%8,%9}, {%0,%1,%2,%3};"
        : "+f"(c[0]), "+f"(c[1]), "+f"(c[2]), "+f"(c[3])
        : "r"(a[0]), "r"(a[1]), "r"(a[2]), "r"(a[3]), "r"(b[0]), "r"(b[1]));
}
__device__ __forceinline__ void ldsm4(uint32_t* r, uint32_t addr) {
    asm volatile("ldmatrix.sync.aligned.m8n8.x4.shared.b16 {%0,%1,%2,%3}, [%4];"
        : "=r"(r[0]), "=r"(r[1]), "=r"(r[2]), "=r"(r[3]) : "r"(addr));
}
__device__ __forceinline__ void ldsm2(uint32_t* r, uint32_t addr) {
    asm volatile("ldmatrix.sync.aligned.m8n8.x2.shared.b16 {%0,%1}, [%2];"
        : "=r"(r[0]), "=r"(r[1]) : "r"(addr));
}
__device__ __forceinline__ void cpa16(uint32_t dst, const void* src) {
    asm volatile("cp.async.cg.shared.global [%0], [%1], 16;"
                 :: "r"(dst), "l"(src) : "memory");
}
__device__ __forceinline__ void cpa16_ca(uint32_t dst, const void* src) {
    asm volatile("cp.async.ca.shared.global [%0], [%1], 16;"
                 :: "r"(dst), "l"(src) : "memory");
}
#define CP_COMMIT() asm volatile("cp.async.commit_group;" ::: "memory")
#define CP_WAIT(n)  asm volatile("cp.async.wait_group %0;" :: "n"(n) : "memory")

// ---------------------------------------------------------------------------
// Split fp32 -> bf16 hi/lo (generic)
// ---------------------------------------------------------------------------
__device__ __forceinline__ void split4(float4 v, uint2& hi, uint2& lo) {
    __nv_bfloat16 h0 = __float2bfloat16(v.x), h1 = __float2bfloat16(v.y);
    __nv_bfloat16 h2 = __float2bfloat16(v.z), h3 = __float2bfloat16(v.w);
    __nv_bfloat16 l0 = __float2bfloat16(v.x - __bfloat162float(h0));
    __nv_bfloat16 l1 = __float2bfloat16(v.y - __bfloat162float(h1));
    __nv_bfloat16 l2 = __float2bfloat16(v.z - __bfloat162float(h2));
    __nv_bfloat16 l3 = __float2bfloat16(v.w - __bfloat162float(h3));
    __nv_bfloat162 ha(h0, h1), hb(h2, h3), la(l0, l1), lb(l2, l3);
    hi.x = *(uint32_t*)&ha; hi.y = *(uint32_t*)&hb;
    lo.x = *(uint32_t*)&la; lo.y = *(uint32_t*)&lb;
}

__global__ void cvt_split(const float* __restrict__ src,
                          __nv_bfloat16* __restrict__ dhi,
                          __nv_bfloat16* __restrict__ dlo) {
    const size_t i = (size_t)blockIdx.x * 256 + threadIdx.x;
    float4 v = *((const float4*)src + i);
    uint2 hi, lo;
    split4(v, hi, lo);
    ((uint2*)dhi)[i] = hi;
    ((uint2*)dlo)[i] = lo;
}

// ---------------------------------------------------------------------------
// Kernel A (HMMA): g_xw[m,g] = sum_i X[m,i]*W[g,i] + bias[g]  (R11 winner)
// ---------------------------------------------------------------------------
#define TCK 64
#define TERM 16384
#define STAGEB 65536
#define NSTG (II / TCK)

__global__ __launch_bounds__(256) void gemm_xw_hmma(const float* __restrict__ bias) {
    extern __shared__ __align__(1024) char dsm[];
    __shared__ float s_bias[128];

    const int tid = threadIdx.x;
    const int wid = tid >> 5;
    const int lid = tid & 31;
    const int wm = wid >> 2;
    const int wn = wid & 3;
    const int n0 = blockIdx.x << 7;
    const int m0 = blockIdx.y << 7;

    const uint32_t smbase = smem_u32(dsm);

    if (tid < 128) s_bias[tid] = bias[n0 + tid];

    const __nv_bfloat16* xh = g_xh + (size_t)m0 * II;
    const __nv_bfloat16* xl = g_xl + (size_t)m0 * II;
    const __nv_bfloat16* wh = g_wh + (size_t)n0 * II;
    const __nv_bfloat16* wl = g_wl + (size_t)n0 * II;

    uint32_t s_off[4];
    size_t g_off[4];
    #pragma unroll
    for (int j = 0; j < 4; j++) {
        const int idx = tid + (j << 8);
        const int r = idx >> 3;
        const int c = idx & 7;
        s_off[j] = SW128((uint32_t)(r * 128 + c * 16));
        g_off[j] = (size_t)r * II + c * 8;
    }

    uint32_t aRowRaw[4], bRowRaw[4];
    #pragma unroll
    for (int mi = 0; mi < 4; mi++)
        aRowRaw[mi] = (uint32_t)(((wm << 6) + (mi << 4) + (lid & 15)) * 128);
    #pragma unroll
    for (int ni = 0; ni < 4; ni++)
        bRowRaw[ni] = (uint32_t)(((wn << 5) + (ni << 3) + (lid & 7)) * 128);
    const uint32_t aChunk = (lid >> 4) << 4;
    const uint32_t bChunk = ((lid >> 3) & 1) << 4;

    float acc[4][4][4];
    #pragma unroll
    for (int mi = 0; mi < 4; mi++)
        #pragma unroll
        for (int ni = 0; ni < 4; ni++)
            #pragma unroll
            for (int q = 0; q < 4; q++) acc[mi][ni][q] = 0.0f;

    {
        const uint32_t sb = smbase;
        #pragma unroll
        for (int j = 0; j < 4; j++) {
            cpa16(sb + s_off[j],            xh + g_off[j]);
            cpa16(sb + TERM + s_off[j],     xl + g_off[j]);
            cpa16(sb + 2 * TERM + s_off[j], wh + g_off[j]);
            cpa16(sb + 3 * TERM + s_off[j], wl + g_off[j]);
        }
        CP_COMMIT();
    }

    for (int s = 0; s < NSTG; s++) {
        if (s + 1 < NSTG) {
            const uint32_t sb = smbase + ((s + 1) & 1) * STAGEB;
            const int k0 = (s + 1) * TCK;
            #pragma unroll
            for (int j = 0; j < 4; j++) {
                cpa16(sb + s_off[j],            xh + g_off[j] + k0);
                cpa16(sb + TERM + s_off[j],     xl + g_off[j] + k0);
                cpa16(sb + 2 * TERM + s_off[j], wh + g_off[j] + k0);
                cpa16(sb + 3 * TERM + s_off[j], wl + g_off[j] + k0);
            }
            CP_COMMIT();
            CP_WAIT(1);
        } else {
            CP_WAIT(0);
        }
        __syncthreads();

        const uint32_t sb = smbase + (s & 1) * STAGEB;
        #pragma unroll
        for (int kc = 0; kc < 4; kc++) {
            uint32_t ah[4][4], al[4][4], bh[4][2], bl[4][2];
            #pragma unroll
            for (int mi = 0; mi < 4; mi++) {
                const uint32_t ao = SW128(aRowRaw[mi] + (kc << 5) + aChunk);
                ldsm4(ah[mi], sb + ao);
                ldsm4(al[mi], sb + TERM + ao);
            }
            #pragma unroll
            for (int ni = 0; ni < 4; ni++) {
                const uint32_t bo = SW128(bRowRaw[ni] + (kc << 5) + bChunk);
                ldsm2(bh[ni], sb + 2 * TERM + bo);
                ldsm2(bl[ni], sb + 3 * TERM + bo);
            }
            #pragma unroll
            for (int mi = 0; mi < 4; mi++)
                #pragma unroll
                for (int ni = 0; ni < 4; ni++) {
                    hmma(acc[mi][ni], ah[mi], bh[ni]);
                    hmma(acc[mi][ni], ah[mi], bl[ni]);
                    hmma(acc[mi][ni], al[mi], bh[ni]);
                }
        }
        __syncthreads();
    }

    #pragma unroll
    for (int mi = 0; mi < 4; mi++) {
        const int mA = m0 + (wm << 6) + (mi << 4) + (lid >> 2);
        #pragma unroll
        for (int ni = 0; ni < 4; ni++) {
            const int colB = (wn << 5) + (ni << 3) + ((lid & 3) << 1);
            const float b0 = s_bias[colB], b1 = s_bias[colB + 1];
            float2 o0 = {acc[mi][ni][0] + b0, acc[mi][ni][1] + b1};
            float2 o1 = {acc[mi][ni][2] + b0, acc[mi][ni][3] + b1};
            *(float2*)(g_xw + (size_t)mA * G4 + n0 + colB)       = o0;
            *(float2*)(g_xw + (size_t)(mA + 8) * G4 + n0 + colB) = o1;
        }
    }
}

// ---------------------------------------------------------------------------
// Kernel B: PERSISTENT LSTM with HMMA phase-1 and U RESIDENT in SMEM.
//   128 blocks (nb=bid>>3, kb=bid&7), 256 threads, single wave.
//   Startup: load B = U_{hi,lo}[256 x 128k] slice ONCE into SMEM (128 KB) —
//     it never changes across steps.
//   Per step:
//     Load A = h_{hi,lo}[64 x 128k] (cp.async.cg, 32 KB, L2-coherent).
//     3-term HMMA 64m x 256n x 128k -> fp32 partials -> g_part[kb].
//     Prefetch xW gate values into registers, then nb-group counter sync.
//     Combine 8 h-cols/block; write h fp32 + bf16 hi/lo. Grid barrier.
// ---------------------------------------------------------------------------
#define A_HI 0
#define A_LO 16384
#define B_HI 32768
#define B_LO 98304
#define SMEMB 163840
#define A_ATOM 8192     // 64 rows * 128B
#define B_ATOM 32768    // 256 rows * 128B

__global__ __launch_bounds__(256) void lstm_persist_tc(float* __restrict__ out) {
    extern __shared__ __align__(1024) char dsm[];

    const int bid = blockIdx.x;
    const int nb = bid >> 3;              // 0..15
    const int kb = bid & 7;               // 0..7
    const int tid = threadIdx.x;
    const int wid = tid >> 5;             // warp = n-slab of 32 cols
    const int lid = tid & 31;

    const uint32_t smbase = smem_u32(dsm);

    // ---- loader precompute ----
    uint32_t aso[4];
    size_t   ago[4];
    #pragma unroll
    for (int j = 0; j < 4; j++) {
        const int idx = tid + (j << 8);
        const int r = idx >> 4, c = idx & 15;
        aso[j] = (uint32_t)((c >> 3) * A_ATOM) +
                 SW128((uint32_t)(r * 128 + (c & 7) * 16));
        ago[j] = (size_t)r * HH + kb * BKC + c * 8;
    }

    // ---- B (U slice) load: ONCE, stays resident ----
    #pragma unroll
    for (int j = 0; j < 16; j++) {
        const int idx = tid + (j << 8);
        const int r = idx >> 4, c = idx & 15;
        const int G = ((r >> 6) << 10) + (nb << 6) + (r & 63);
        const uint32_t bso = (uint32_t)((c >> 3) * B_ATOM) +
                             SW128((uint32_t)(r * 128 + (c & 7) * 16));
        const size_t bgo = (size_t)G * HH + kb * BKC + c * 8;
        cpa16_ca(smbase + B_HI + bso, g_uh + bgo);
        cpa16_ca(smbase + B_LO + bso, g_ul + bgo);
    }
    CP_COMMIT();

    // ldmatrix row bases
    uint32_t aRowRaw[4], bRowRaw[4];
    #pragma unroll
    for (int mi = 0; mi < 4; mi++)
        aRowRaw[mi] = (uint32_t)(((mi << 4) + (lid & 15)) * 128);
    #pragma unroll
    for (int ni = 0; ni < 4; ni++)
        bRowRaw[ni] = (uint32_t)(((wid << 5) + (ni << 3) + (lid & 7)) * 128);
    const uint32_t aChunk = (lid >> 4) << 4;
    const uint32_t bChunk = ((lid >> 3) & 1) << 4;

    // combine indices: 8 h-cols per block
    const int cb  = tid >> 2;
    const int hcol = (nb << 6) + (kb << 3) + ((tid & 3) << 1);

    CP_WAIT(0);
    __syncthreads();

    for (int t = 0; t < SS; t++) {
        const int par = t & 1;

        // ---------------- load A tile (h hi/lo) ----------------
        #pragma unroll
        for (int j = 0; j < 4; j++) {
            cpa16(smbase + A_HI + aso[j], g_hh + ago[j]);
            cpa16(smbase + A_LO + aso[j], g_hl + ago[j]);
        }
        CP_COMMIT();
        CP_WAIT(0);
        __syncthreads();

        // ---------------- HMMA: 64m x 256n x 128k, 3 terms ----------------
        float acc[4][4][4];
        #pragma unroll
        for (int mi = 0; mi < 4; mi++)
            #pragma unroll
            for (int ni = 0; ni < 4; ni++)
                #pragma unroll
                for (int q = 0; q < 4; q++) acc[mi][ni][q] = 0.0f;

        #pragma unroll
        for (int kk = 0; kk < 8; kk++) {
            const uint32_t aAt = (uint32_t)((kk >> 2) * A_ATOM);
            const uint32_t bAt = (uint32_t)((kk >> 2) * B_ATOM);
            const uint32_t kco = (uint32_t)((kk & 3) << 5);

            uint32_t ah[4][4], al[4][4], bh[4][2], bl[4][2];
            #pragma unroll
            for (int mi = 0; mi < 4; mi++) {
                const uint32_t ao = aAt + SW128(aRowRaw[mi] + kco + aChunk);
                ldsm4(ah[mi], smbase + A_HI + ao);
                ldsm4(al[mi], smbase + A_LO + ao);
            }
            #pragma unroll
            for (int ni = 0; ni < 4; ni++) {
                const uint32_t bo = bAt + SW128(bRowRaw[ni] + kco + bChunk);
                ldsm2(bh[ni], smbase + B_HI + bo);
                ldsm2(bl[ni], smbase + B_LO + bo);
            }
            #pragma unroll
            for (int mi = 0; mi < 4; mi++)
                #pragma unroll
                for (int ni = 0; ni < 4; ni++) {
                    hmma(acc[mi][ni], ah[mi], bh[ni]);
                    hmma(acc[mi][ni], ah[mi], bl[ni]);
                    hmma(acc[mi][ni], al[mi], bh[ni]);
                }
        }
        __syncthreads();   // A smem reuse next step (single buffer)

        // ---------------- store partials ----------------
        {
            float* pout = g_part[kb];
            #pragma unroll
            for (int mi = 0; mi < 4; mi++) {
                const int m = (mi << 4) + (lid >> 2);
                #pragma unroll
                for (int ni = 0; ni < 4; ni++) {
                    const int c = (wid << 5) + (ni << 3) + ((lid & 3) << 1);
                    const int G = ((c >> 6) << 10) + (nb << 6) + (c & 63);
                    float2 o0 = {acc[mi][ni][0], acc[mi][ni][1]};
                    float2 o1 = {acc[mi][ni][2], acc[mi][ni][3]};
                    *(float2*)(pout + (size_t)m * G4 + G)       = o0;
                    *(float2*)(pout + (size_t)(m + 8) * G4 + G) = o1;
                }
            }
        }

        __threadfence();

        // Prefetch xW gate values (independent of partials) — in flight
        // while we spin on the nb counter.
        float2 gate[4];
        #pragma unroll
        for (int g = 0; g < 4; g++) {
            const size_t off = (size_t)cb * G4 + (g << 10) + hcol;
            gate[g] = *(const float2*)(g_xw + (size_t)t * BB * G4 + off);
        }

        // ---------------- nb-group sync ----------------
        __syncthreads();
        if (tid == 0) {
            atomicAdd(&g_nbcnt[nb], 1u);
            while (atomicAdd(&g_nbcnt[nb], 0u) < 8u * (unsigned)(t + 1)) {
                __nanosleep(32);
            }
        }
        __syncthreads();

        // ---------------- combine + elementwise ----------------
        {
            #pragma unroll
            for (int g = 0; g < 4; g++) {
                const size_t off = (size_t)cb * G4 + (g << 10) + hcol;
                #pragma unroll
                for (int p = 0; p < NKB; p++) {
                    const float2 pv = __ldcg((const float2*)(g_part[p] + off));
                    gate[g].x += pv.x; gate[g].y += pv.y;
                }
            }

            const int idx = cb * HH + hcol;
            const float2 cp = *(const float2*)(g_c[par] + idx);
            float2 cn, hv;
            {
                const float iv = sigf(gate[0].x), fv = sigf(gate[1].x);
                const float gv = tanhfast(gate[2].x), ov = sigf(gate[3].x);
                cn.x = fv * cp.x + iv * gv;  hv.x = ov * tanhfast(cn.x);
            }
            {
                const float iv = sigf(gate[0].y), fv = sigf(gate[1].y);
                const float gv = tanhfast(gate[2].y), ov = sigf(gate[3].y);
                cn.y = fv * cp.y + iv * gv;  hv.y = ov * tanhfast(cn.y);
            }
            *(float2*)(g_c[par ^ 1] + idx) = cn;
            *(float2*)(out + (size_t)t * BHH + idx) = hv;

            __nv_bfloat16 h0b = __float2bfloat16(hv.x);
            __nv_bfloat16 h1b = __float2bfloat16(hv.y);
            __nv_bfloat16 l0b = __float2bfloat16(hv.x - __bfloat162float(h0b));
            __nv_bfloat16 l1b = __float2bfloat16(hv.y - __bfloat162float(h1b));
            __nv_bfloat162 hp(h0b, h1b), lp(l0b, l1b);
            *(__nv_bfloat162*)(g_hh + idx) = hp;
            *(__nv_bfloat162*)(g_hl + idx) = lp;
        }

        // ---------------- grid step barrier ----------------
        __threadfence();
        __syncthreads();
        if (tid == 0) {
            atomicAdd(&g_stepcnt, 1u);
            if (t + 1 < SS) {
                while (atomicAdd(&g_stepcnt, 0u) < 128u * (unsigned)(t + 1)) {
                    __nanosleep(32);
                }
            }
        }
        __syncthreads();
    }
}

// ---------------------------------------------------------------------------
// Helpers
// ---------------------------------------------------------------------------
__global__ void seed_state(const float* __restrict__ c0,
                           const float* __restrict__ h0) {
    const int i = blockIdx.x * 256 + threadIdx.x;
    g_c[0][i] = c0[i];
    const float h = h0[i];
    const __nv_bfloat16 hh = __float2bfloat16(h);
    g_hh[i] = hh;
    g_hl[i] = __float2bfloat16(h - __bfloat162float(hh));
    if (blockIdx.x == 0) {
        if (threadIdx.x < NNB) g_nbcnt[threadIdx.x] = 0u;
        if (threadIdx.x == NNB) g_stepcnt = 0u;
    }
}

__global__ void finalize(float* __restrict__ out) {
    const int i = blockIdx.x * 256 + threadIdx.x;
    const size_t base = (size_t)SS * BHH;
    out[base + i] = out[(size_t)(SS - 1) * BHH + i];   // h_t
    out[base + BHH + i] = g_c[0][i];                   // c_t (S even)
}

// ---------------------------------------------------------------------------
extern "C" void kernel_launch(void* const* d_in, const int* in_sizes, int n_in,
                              void* d_out, int out_size) {
    (void)in_sizes; (void)n_in; (void)out_size;
    const float* x  = (const float*)d_in[0];
    const float* h0 = (const float*)d_in[1];
    const float* c0 = (const float*)d_in[2];
    const float* Ww = (const float*)d_in[3];
    const float* Wb = (const float*)d_in[4];
    const float* Uw = (const float*)d_in[5];
    float* out = (float*)d_out;

    cudaFuncSetAttribute(gemm_xw_hmma,
                         cudaFuncAttributeMaxDynamicSharedMemorySize,
                         2 * STAGEB);
    cudaFuncSetAttribute(lstm_persist_tc,
                         cudaFuncAttributeMaxDynamicSharedMemorySize,
                         SMEMB);

    seed_state<<<BHH / 256, 256>>>(c0, h0);

    __nv_bfloat16 *xh, *xl, *wh, *wl, *uh, *ul;
    cudaGetSymbolAddress((void**)&xh, g_xh);
    cudaGetSymbolAddress((void**)&xl, g_xl);
    cudaGetSymbolAddress((void**)&wh, g_wh);
    cudaGetSymbolAddress((void**)&wl, g_wl);
    cudaGetSymbolAddress((void**)&uh, g_uh);
    cudaGetSymbolAddress((void**)&ul, g_ul);

    cvt_split<<<(SS * BB * II / 4) / 256, 256>>>(x, xh, xl);
    cvt_split<<<(G4 * II / 4) / 256, 256>>>(Ww, wh, wl);
    cvt_split<<<(G4 * HH / 4) / 256, 256>>>(Uw, uh, ul);

    gemm_xw_hmma<<<dim3(G4 / 128, (SS * BB) / 128), 256, 2 * STAGEB>>>(Wb);

    lstm_persist_tc<<<NNB * NKB, 256, SMEMB>>>(out);

    finalize<<<BHH / 256, 256>>>(out);
}